// round 1
// baseline (speedup 1.0000x reference)
#include <cuda_runtime.h>
#include <cstdint>
#include <cstddef>

namespace {
constexpr int kB = 16;
constexpr int kS = 2048;
constexpr int kD = 128;
constexpr int TQ = 64;
constexpr int TK = 64;
constexpr int NT = 256;            // threads per block
constexpr int NKT = kS / TK;       // 32 k-tiles
constexpr int DP = kD + 4;         // padded pitch for D-major tiles (132)
constexpr int KP = TK + 4;         // padded pitch for P tile (68)
constexpr float kScale = 0.08838834764831845f;  // 1/sqrt(128)

struct Smem {
  float Qs[TQ][DP];   // Q tile   [r][d]
  float Ks[TK][DP];   // K tile   [c][d]
  float Vs[TK][DP];   // V tile   [c][d]
  float Ps[TQ][KP];   // exp tile [r][c]
  float Zs[TQ];       // row sums
  float rZs[TQ];      // reciprocal row sums
};
constexpr int SMEM_BYTES = (int)sizeof(Smem);
}  // namespace

extern "C" __global__ void __launch_bounds__(NT, 1)
sdpa_kernel(const float* __restrict__ Q, const float* __restrict__ K,
            const float* __restrict__ V, float* __restrict__ out,
            float* __restrict__ attn)
{
  extern __shared__ char smem_raw[];
  Smem& sm = *reinterpret_cast<Smem*>(smem_raw);

  const int qt  = blockIdx.x;        // q tile (heavy tiles scheduled first)
  const int b   = blockIdx.y;        // batch
  const int tid = threadIdx.x;
  const int tr  = tid >> 4;          // 0..15 (row group)
  const int tc  = tid & 15;          // 0..15 (col group)
  const int q0  = qt * TQ;

  const float* Qb = Q + (size_t)b * kS * kD;
  const float* Kb = K + (size_t)b * kS * kD;
  const float* Vb = V + (size_t)b * kS * kD;
  float* outb  = out  + (size_t)b * kS * kD;
  float* attnb = attn + (size_t)b * kS * kS;

  // ---- Load Q tile (rows q0..q0+63) ----
  {
    const float4* Qg = reinterpret_cast<const float4*>(Qb + (size_t)q0 * kD);
#pragma unroll
    for (int it = 0; it < (TQ * kD / 4) / NT; ++it) {
      int idx = tid + it * NT;       // 0..2047
      int r = idx >> 5;              // 32 float4 per row
      int c4 = idx & 31;
      *reinterpret_cast<float4*>(&sm.Qs[r][c4 * 4]) = Qg[idx];
    }
  }
  // Z init: masked entries (k<=q) each contribute exp(0)=1 -> (q+1)
  for (int r = tid; r < TQ; r += NT) sm.Zs[r] = (float)(q0 + r + 1);

  // per-thread output accumulators: rows 4*tr+i, dcols 8*tc+jj  (unnormalized)
  float acc[4][8];
#pragma unroll
  for (int i = 0; i < 4; ++i)
#pragma unroll
    for (int j = 0; j < 8; ++j) acc[i][j] = 0.f;
  float vsum[8];
#pragma unroll
  for (int j = 0; j < 8; ++j) vsum[j] = 0.f;

  // ================= Phase 1: upper (incl. diagonal) k-tiles =================
  for (int kt = qt; kt < NKT; ++kt) {
    const int k0 = kt * TK;
    __syncthreads();  // protect Ks/Vs/Ps reuse from previous iteration
    {
      const float4* Kg = reinterpret_cast<const float4*>(Kb + (size_t)k0 * kD);
      const float4* Vg = reinterpret_cast<const float4*>(Vb + (size_t)k0 * kD);
#pragma unroll
      for (int it = 0; it < (TK * kD / 4) / NT; ++it) {
        int idx = tid + it * NT;
        int r = idx >> 5;
        int c4 = idx & 31;
        *reinterpret_cast<float4*>(&sm.Ks[r][c4 * 4]) = Kg[idx];
        *reinterpret_cast<float4*>(&sm.Vs[r][c4 * 4]) = Vg[idx];
      }
    }
    __syncthreads();

    // ---- scores: rows 4*tr+i, cols tc+16*j ----
    float sacc[4][4];
#pragma unroll
    for (int i = 0; i < 4; ++i)
#pragma unroll
      for (int j = 0; j < 4; ++j) sacc[i][j] = 0.f;

#pragma unroll 8
    for (int d = 0; d < kD; ++d) {
      float qv[4], kv[4];
#pragma unroll
      for (int i = 0; i < 4; ++i) qv[i] = sm.Qs[4 * tr + i][d];
#pragma unroll
      for (int j = 0; j < 4; ++j) kv[j] = sm.Ks[tc + 16 * j][d];
#pragma unroll
      for (int i = 0; i < 4; ++i)
#pragma unroll
        for (int j = 0; j < 4; ++j)
          sacc[i][j] = fmaf(qv[i], kv[j], sacc[i][j]);
    }

    // ---- mask + exp; stage to smem P; write unnormalized E to gmem ----
    float rowsum[4] = {0.f, 0.f, 0.f, 0.f};
    const bool diag = (kt == qt);
#pragma unroll
    for (int i = 0; i < 4; ++i) {
      const int r = 4 * tr + i;
      float* arow = attnb + (size_t)(q0 + r) * kS + k0;
#pragma unroll
      for (int j = 0; j < 4; ++j) {
        const int c = tc + 16 * j;
        float e;
        if (diag && c <= r) {
          e = 1.0f;                        // masked -> exp(0); counted in Z init
        } else {
          e = __expf(sacc[i][j] * kScale);
          rowsum[i] += e;
        }
        sm.Ps[r][c] = e;
        arow[c] = e;                       // unnormalized; rescaled in phase 2
      }
    }
    // deterministic row-sum reduction across the 16 tc lanes of each half-warp
#pragma unroll
    for (int i = 0; i < 4; ++i) {
      float v = rowsum[i];
      v += __shfl_down_sync(0xffffffffu, v, 8, 16);
      v += __shfl_down_sync(0xffffffffu, v, 4, 16);
      v += __shfl_down_sync(0xffffffffu, v, 2, 16);
      v += __shfl_down_sync(0xffffffffu, v, 1, 16);
      if (tc == 0) sm.Zs[4 * tr + i] += v;   // unique owner per row -> race-free
    }
    __syncthreads();  // Ps complete before PV

    // ---- out += P @ V (unnormalized) ----
#pragma unroll 2
    for (int c = 0; c < TK; ++c) {
      float p[4];
#pragma unroll
      for (int i = 0; i < 4; ++i) p[i] = sm.Ps[4 * tr + i][c];
      const float4 va = *reinterpret_cast<const float4*>(&sm.Vs[c][8 * tc]);
      const float4 vb = *reinterpret_cast<const float4*>(&sm.Vs[c][8 * tc + 4]);
      float v8[8] = {va.x, va.y, va.z, va.w, vb.x, vb.y, vb.z, vb.w};
#pragma unroll
      for (int i = 0; i < 4; ++i)
#pragma unroll
        for (int j = 0; j < 8; ++j)
          acc[i][j] = fmaf(p[i], v8[j], acc[i][j]);
    }
  }

  // ================= Phase 2 =================
  __syncthreads();
  for (int r = tid; r < TQ; r += NT) sm.rZs[r] = 1.0f / sm.Zs[r];
  __syncthreads();

  // ---- lower k-tiles: attention = 1/Z fill; accumulate V column prefix sums ----
  for (int kt = 0; kt < qt; ++kt) {
    const int k0 = kt * TK;
    __syncthreads();  // protect Vs from previous vsum reads
    {
      const float4* Vg = reinterpret_cast<const float4*>(Vb + (size_t)k0 * kD);
#pragma unroll
      for (int it = 0; it < (TK * kD / 4) / NT; ++it) {
        int idx = tid + it * NT;
        int r = idx >> 5;
        int c4 = idx & 31;
        *reinterpret_cast<float4*>(&sm.Vs[r][c4 * 4]) = Vg[idx];
      }
    }
    __syncthreads();
#pragma unroll 4
    for (int c = 0; c < TK; ++c) {
      const float4 va = *reinterpret_cast<const float4*>(&sm.Vs[c][8 * tc]);
      const float4 vb = *reinterpret_cast<const float4*>(&sm.Vs[c][8 * tc + 4]);
      vsum[0] += va.x; vsum[1] += va.y; vsum[2] += va.z; vsum[3] += va.w;
      vsum[4] += vb.x; vsum[5] += vb.y; vsum[6] += vb.z; vsum[7] += vb.w;
    }
    // fill attention tile with per-row 1/Z
#pragma unroll
    for (int p = 0; p < 4; ++p) {
      const int r = tr + 16 * p;
      const float rz = sm.rZs[r];
      const float4 f = make_float4(rz, rz, rz, rz);
      *reinterpret_cast<float4*>(&attnb[(size_t)(q0 + r) * kS + k0 + 4 * tc]) = f;
    }
  }

  // ---- rescale upper tiles: attn = E * (1/Z) ----
  for (int kt = qt; kt < NKT; ++kt) {
    const int k0 = kt * TK;
#pragma unroll
    for (int p = 0; p < 4; ++p) {
      const int r = tr + 16 * p;
      const float rz = sm.rZs[r];
      float4* a = reinterpret_cast<float4*>(&attnb[(size_t)(q0 + r) * kS + k0 + 4 * tc]);
      float4 v = *a;
      v.x *= rz; v.y *= rz; v.z *= rz; v.w *= rz;
      *a = v;
    }
  }

  // ---- final output: rZ * (upper PV acc + lower V prefix sum) ----
#pragma unroll
  for (int i = 0; i < 4; ++i) {
    const int r = 4 * tr + i;
    const float rz = sm.rZs[r];
    float4 o0, o1;
    o0.x = rz * (acc[i][0] + vsum[0]);
    o0.y = rz * (acc[i][1] + vsum[1]);
    o0.z = rz * (acc[i][2] + vsum[2]);
    o0.w = rz * (acc[i][3] + vsum[3]);
    o1.x = rz * (acc[i][4] + vsum[4]);
    o1.y = rz * (acc[i][5] + vsum[5]);
    o1.z = rz * (acc[i][6] + vsum[6]);
    o1.w = rz * (acc[i][7] + vsum[7]);
    float* dst = &outb[(size_t)(q0 + r) * kD + 8 * tc];
    *reinterpret_cast<float4*>(dst)     = o0;
    *reinterpret_cast<float4*>(dst + 4) = o1;
  }
}

extern "C" void kernel_launch(void* const* d_in, const int* in_sizes, int n_in,
                              void* d_out, int out_size) {
  (void)in_sizes; (void)n_in; (void)out_size;
  const float* Q = (const float*)d_in[0];
  const float* K = (const float*)d_in[1];
  const float* V = (const float*)d_in[2];
  float* out  = (float*)d_out;
  float* attn = out + (size_t)kB * kS * kD;   // tuple order: (output, attention)

  cudaFuncSetAttribute(sdpa_kernel, cudaFuncAttributeMaxDynamicSharedMemorySize,
                       SMEM_BYTES);
  dim3 grid(NKT, kB);   // qt fastest -> heaviest blocks scheduled first
  sdpa_kernel<<<grid, NT, SMEM_BYTES>>>(Q, K, V, out, attn);
}

// round 2
// speedup vs baseline: 2.4282x; 2.4282x over previous
#include <cuda_runtime.h>
#include <cstdint>
#include <cstddef>

namespace {
constexpr int kB = 16;
constexpr int kS = 2048;
constexpr int kD = 128;
constexpr int TQ = 64;
constexpr int TK = 64;
constexpr int NT = 256;            // 8 warps
constexpr int NKT = kS / TK;       // 32 k-tiles
constexpr int DP = kD + 4;         // pitch 132 (132 % 32 == 4 -> conflict-free frags)
constexpr int KP = TK + 4;         // pitch 68  (68 % 32 == 4)
constexpr float kScale = 0.08838834764831845f;  // 1/sqrt(128)

struct Smem {
  float Qs[TQ][DP];      // Q tile (tf32-rounded)
  float Ks[TK][DP];      // K tile (tf32-rounded)
  float Vs[TK][DP];      // V tile (tf32 in phase1, raw fp32 in phase2)
  float Ps[TQ][KP];      // exp tile (tf32-rounded)
  float Zs[TQ];
  float rZs[TQ];
  float Vps[2][kD];      // partial V column sums (lower triangle)
  float Vcsum[kD];
};
constexpr int SMEM_BYTES = (int)sizeof(Smem);

__device__ __forceinline__ uint32_t f2tf32(float f) {
  uint32_t u;
  asm("cvt.rna.tf32.f32 %0, %1;" : "=r"(u) : "f"(f));
  return u;
}

__device__ __forceinline__ void mma_tf32(float c[4], uint32_t a0, uint32_t a1,
                                         uint32_t a2, uint32_t a3,
                                         uint32_t b0, uint32_t b1) {
  asm volatile(
      "mma.sync.aligned.m16n8k8.row.col.f32.tf32.tf32.f32 "
      "{%0,%1,%2,%3}, {%4,%5,%6,%7}, {%8,%9}, {%0,%1,%2,%3};\n"
      : "+f"(c[0]), "+f"(c[1]), "+f"(c[2]), "+f"(c[3])
      : "r"(a0), "r"(a1), "r"(a2), "r"(a3), "r"(b0), "r"(b1));
}

__device__ __forceinline__ uint32_t ldu(const float* p) {
  return __float_as_uint(*p);
}
}  // namespace

extern "C" __global__ void __launch_bounds__(NT, 1)
sdpa_kernel(const float* __restrict__ Q, const float* __restrict__ K,
            const float* __restrict__ V, float* __restrict__ out,
            float* __restrict__ attn)
{
  extern __shared__ char smem_raw[];
  Smem& sm = *reinterpret_cast<Smem*>(smem_raw);

  const int qt  = blockIdx.x;
  const int b   = blockIdx.y;
  const int tid = threadIdx.x;
  const int q0  = qt * TQ;

  const int wid  = tid >> 5;        // 0..7
  const int lane = tid & 31;
  const int wr   = wid >> 1;        // 0..3  (16-row band)
  const int wc   = wid & 1;         // 0..1
  const int gid  = lane >> 2;       // 0..7
  const int tig  = lane & 3;        // 0..3

  const float* Qb = Q + (size_t)b * kS * kD;
  const float* Kb = K + (size_t)b * kS * kD;
  const float* Vb = V + (size_t)b * kS * kD;
  float* outb  = out  + (size_t)b * kS * kD;
  float* attnb = attn + (size_t)b * kS * kS;

  // ---- Load + tf32-round Q tile ----
  {
    const float4* Qg = reinterpret_cast<const float4*>(Qb + (size_t)q0 * kD);
#pragma unroll
    for (int it = 0; it < (TQ * kD / 4) / NT; ++it) {
      int idx = tid + it * NT;
      int r = idx >> 5, c4 = idx & 31;
      float4 v = Qg[idx];
      v.x = __uint_as_float(f2tf32(v.x));
      v.y = __uint_as_float(f2tf32(v.y));
      v.z = __uint_as_float(f2tf32(v.z));
      v.w = __uint_as_float(f2tf32(v.w));
      *reinterpret_cast<float4*>(&sm.Qs[r][c4 * 4]) = v;
    }
  }
  // Z init: lower tiles contribute q0 masked ones; diag-tile ones are summed in Ps.
  for (int r = tid; r < TQ; r += NT) sm.Zs[r] = (float)q0;

  // PV accumulators: warp tile 16 rows x 64 cols -> per thread 8 n-blocks x 4
  float oacc[8][4];
#pragma unroll
  for (int j = 0; j < 8; ++j)
#pragma unroll
    for (int v = 0; v < 4; ++v) oacc[j][v] = 0.f;

  // ================= Phase 1: upper (incl diagonal) tiles =================
  for (int kt = qt; kt < NKT; ++kt) {
    const int k0 = kt * TK;
    __syncthreads();
    {
      const float4* Kg = reinterpret_cast<const float4*>(Kb + (size_t)k0 * kD);
      const float4* Vg = reinterpret_cast<const float4*>(Vb + (size_t)k0 * kD);
#pragma unroll
      for (int it = 0; it < (TK * kD / 4) / NT; ++it) {
        int idx = tid + it * NT;
        int r = idx >> 5, c4 = idx & 31;
        float4 kv = Kg[idx];
        kv.x = __uint_as_float(f2tf32(kv.x));
        kv.y = __uint_as_float(f2tf32(kv.y));
        kv.z = __uint_as_float(f2tf32(kv.z));
        kv.w = __uint_as_float(f2tf32(kv.w));
        *reinterpret_cast<float4*>(&sm.Ks[r][c4 * 4]) = kv;
        float4 vv = Vg[idx];
        vv.x = __uint_as_float(f2tf32(vv.x));
        vv.y = __uint_as_float(f2tf32(vv.y));
        vv.z = __uint_as_float(f2tf32(vv.z));
        vv.w = __uint_as_float(f2tf32(vv.w));
        *reinterpret_cast<float4*>(&sm.Vs[r][c4 * 4]) = vv;
      }
    }
    __syncthreads();

    // ---- QK^T via mma: warp tile rows 16*wr..+16, cols 32*wc..+32 ----
    float sacc[4][4];
#pragma unroll
    for (int j = 0; j < 4; ++j)
#pragma unroll
      for (int v = 0; v < 4; ++v) sacc[j][v] = 0.f;

    const int ar0 = 16 * wr + gid;
#pragma unroll
    for (int d0 = 0; d0 < kD; d0 += 8) {
      uint32_t a0 = ldu(&sm.Qs[ar0][d0 + tig]);
      uint32_t a1 = ldu(&sm.Qs[ar0 + 8][d0 + tig]);
      uint32_t a2 = ldu(&sm.Qs[ar0][d0 + tig + 4]);
      uint32_t a3 = ldu(&sm.Qs[ar0 + 8][d0 + tig + 4]);
#pragma unroll
      for (int j = 0; j < 4; ++j) {
        const int c0 = 32 * wc + 8 * j;
        uint32_t b0 = ldu(&sm.Ks[c0 + gid][d0 + tig]);
        uint32_t b1 = ldu(&sm.Ks[c0 + gid][d0 + tig + 4]);
        mma_tf32(sacc[j], a0, a1, a2, a3, b0, b1);
      }
    }

    // ---- mask + exp -> Ps (tf32-rounded) ----
    const bool diag = (kt == qt);
#pragma unroll
    for (int j = 0; j < 4; ++j) {
      const int c = 32 * wc + 8 * j + 2 * tig;
      const int r0 = 16 * wr + gid, r1 = r0 + 8;
      float e00, e01, e10, e11;
      if (diag) {
        e00 = (c     > r0) ? __expf(sacc[j][0] * kScale) : 1.0f;
        e01 = (c + 1 > r0) ? __expf(sacc[j][1] * kScale) : 1.0f;
        e10 = (c     > r1) ? __expf(sacc[j][2] * kScale) : 1.0f;
        e11 = (c + 1 > r1) ? __expf(sacc[j][3] * kScale) : 1.0f;
      } else {
        e00 = __expf(sacc[j][0] * kScale);
        e01 = __expf(sacc[j][1] * kScale);
        e10 = __expf(sacc[j][2] * kScale);
        e11 = __expf(sacc[j][3] * kScale);
      }
      float2 p0 = make_float2(__uint_as_float(f2tf32(e00)),
                              __uint_as_float(f2tf32(e01)));
      float2 p1 = make_float2(__uint_as_float(f2tf32(e10)),
                              __uint_as_float(f2tf32(e11)));
      *reinterpret_cast<float2*>(&sm.Ps[r0][c]) = p0;
      *reinterpret_cast<float2*>(&sm.Ps[r1][c]) = p1;
    }
    __syncthreads();

    // ---- Z row sums (deterministic: fixed owner thread per row) ----
    {
      const int r = tid >> 2;
      const int seg = (tid & 3) * 16;
      float s = 0.f;
#pragma unroll
      for (int i = 0; i < 16; ++i) s += sm.Ps[r][seg + i];
      s += __shfl_down_sync(0xffffffffu, s, 2, 4);
      s += __shfl_down_sync(0xffffffffu, s, 1, 4);
      if ((tid & 3) == 0) sm.Zs[r] += s;
    }

    // ---- copy unnormalized E tile to attention gmem ----
    {
#pragma unroll
      for (int it = 0; it < 4; ++it) {
        int idx = tid + it * NT;           // 0..1023 float4s
        int r = idx >> 4, c4 = idx & 15;
        float4 v = *reinterpret_cast<const float4*>(&sm.Ps[r][c4 * 4]);
        *reinterpret_cast<float4*>(&attnb[(size_t)(q0 + r) * kS + k0 + 4 * c4]) = v;
      }
    }

    // ---- PV via mma: warp tile rows 16*wr..+16, cols 64*wc..+64 ----
#pragma unroll
    for (int kk = 0; kk < TK; kk += 8) {
      uint32_t a0 = ldu(&sm.Ps[ar0][kk + tig]);
      uint32_t a1 = ldu(&sm.Ps[ar0 + 8][kk + tig]);
      uint32_t a2 = ldu(&sm.Ps[ar0][kk + tig + 4]);
      uint32_t a3 = ldu(&sm.Ps[ar0 + 8][kk + tig + 4]);
#pragma unroll
      for (int j = 0; j < 8; ++j) {
        const int c0 = 64 * wc + 8 * j;
        uint32_t b0 = ldu(&sm.Vs[kk + tig][c0 + gid]);
        uint32_t b1 = ldu(&sm.Vs[kk + tig + 4][c0 + gid]);
        mma_tf32(oacc[j], a0, a1, a2, a3, b0, b1);
      }
    }
  }

  // ================= Phase 2 =================
  __syncthreads();
  for (int r = tid; r < TQ; r += NT) sm.rZs[r] = 1.0f / sm.Zs[r];
  __syncthreads();

  // ---- lower tiles: V column sums (full fp32) + attn = 1/Z fill ----
  const int vc   = tid & 127;        // column this thread sums
  const int vhalf = tid >> 7;        // 0/1: which 32-row half
  float vpart = 0.f;
  const int tr = tid >> 4, tc = tid & 15;
  for (int kt = 0; kt < qt; ++kt) {
    const int k0 = kt * TK;
    __syncthreads();
    {
      const float4* Vg = reinterpret_cast<const float4*>(Vb + (size_t)k0 * kD);
#pragma unroll
      for (int it = 0; it < (TK * kD / 4) / NT; ++it) {
        int idx = tid + it * NT;
        int r = idx >> 5, c4 = idx & 31;
        *reinterpret_cast<float4*>(&sm.Vs[r][c4 * 4]) = Vg[idx];
      }
    }
    __syncthreads();
#pragma unroll 8
    for (int r = 0; r < 32; ++r) vpart += sm.Vs[32 * vhalf + r][vc];
    // fill attention tile with per-row 1/Z
#pragma unroll
    for (int p = 0; p < 4; ++p) {
      const int r = tr + 16 * p;
      const float rz = sm.rZs[r];
      *reinterpret_cast<float4*>(&attnb[(size_t)(q0 + r) * kS + k0 + 4 * tc]) =
          make_float4(rz, rz, rz, rz);
    }
  }
  sm.Vps[vhalf][vc] = vpart;
  __syncthreads();
  if (tid < kD) sm.Vcsum[tid] = sm.Vps[0][tid] + sm.Vps[1][tid];
  __syncthreads();

  // ---- rescale upper tiles: attn *= 1/Z ----
  for (int kt = qt; kt < NKT; ++kt) {
    const int k0 = kt * TK;
#pragma unroll
    for (int p = 0; p < 4; ++p) {
      const int r = tr + 16 * p;
      const float rz = sm.rZs[r];
      float4* a = reinterpret_cast<float4*>(
          &attnb[(size_t)(q0 + r) * kS + k0 + 4 * tc]);
      float4 v = *a;
      v.x *= rz; v.y *= rz; v.z *= rz; v.w *= rz;
      *a = v;
    }
  }

  // ---- final output from mma accumulators ----
  {
    const int r0 = 16 * wr + gid, r1 = r0 + 8;
    const float rz0 = sm.rZs[r0], rz1 = sm.rZs[r1];
#pragma unroll
    for (int j = 0; j < 8; ++j) {
      const int c = 64 * wc + 8 * j + 2 * tig;
      const float vs0 = sm.Vcsum[c], vs1 = sm.Vcsum[c + 1];
      float2 o0 = make_float2(rz0 * (oacc[j][0] + vs0),
                              rz0 * (oacc[j][1] + vs1));
      float2 o1 = make_float2(rz1 * (oacc[j][2] + vs0),
                              rz1 * (oacc[j][3] + vs1));
      *reinterpret_cast<float2*>(&outb[(size_t)(q0 + r0) * kD + c]) = o0;
      *reinterpret_cast<float2*>(&outb[(size_t)(q0 + r1) * kD + c]) = o1;
    }
  }
}

extern "C" void kernel_launch(void* const* d_in, const int* in_sizes, int n_in,
                              void* d_out, int out_size) {
  (void)in_sizes; (void)n_in; (void)out_size;
  const float* Q = (const float*)d_in[0];
  const float* K = (const float*)d_in[1];
  const float* V = (const float*)d_in[2];
  float* out  = (float*)d_out;
  float* attn = out + (size_t)kB * kS * kD;

  cudaFuncSetAttribute(sdpa_kernel, cudaFuncAttributeMaxDynamicSharedMemorySize,
                       SMEM_BYTES);
  dim3 grid(NKT, kB);
  sdpa_kernel<<<grid, NT, SMEM_BYTES>>>(Q, K, V, out, attn);
}

// round 3
// speedup vs baseline: 2.7482x; 1.1318x over previous
#include <cuda_runtime.h>
#include <cstdint>
#include <cstddef>

namespace {
constexpr int kB = 16;
constexpr int kS = 2048;
constexpr int kD = 128;
constexpr int TQ = 64;
constexpr int TK = 64;
constexpr int NT = 256;            // 8 warps
constexpr int NKT = kS / TK;       // 32 k-tiles
constexpr int DP = kD + 4;         // K pitch 132 (conflict-free QK B-frags)
constexpr int VP = kD + 8;         // V pitch 136 (conflict-free PV B-frags)
constexpr int KP = TK + 4;         // P pitch 68
constexpr float kScale = 0.08838834764831845f;  // 1/sqrt(128)

struct Smem {
  float Ks[2][TK][DP];   // raw fp32 K tiles (double buffered)
  float Vs[2][TK][VP];   // raw fp32 V tiles (double buffered)
  float Ps[TQ][KP];      // tf32-rounded exp tile
  float Zs[TQ];
  float rZs[TQ];
  float Zp[2][TQ];       // per-warp-column Z partials (deterministic 2-slot)
  float Vps[2][kD];
  float Vcsum[kD];
};
constexpr int SMEM_BYTES = (int)sizeof(Smem);

__device__ __forceinline__ uint32_t f2tf32(float f) {
  uint32_t u;
  asm("cvt.rna.tf32.f32 %0, %1;" : "=r"(u) : "f"(f));
  return u;
}

__device__ __forceinline__ void mma_tf32(float c[4], uint32_t a0, uint32_t a1,
                                         uint32_t a2, uint32_t a3,
                                         uint32_t b0, uint32_t b1) {
  asm volatile(
      "mma.sync.aligned.m16n8k8.row.col.f32.tf32.tf32.f32 "
      "{%0,%1,%2,%3}, {%4,%5,%6,%7}, {%8,%9}, {%0,%1,%2,%3};\n"
      : "+f"(c[0]), "+f"(c[1]), "+f"(c[2]), "+f"(c[3])
      : "r"(a0), "r"(a1), "r"(a2), "r"(a3), "r"(b0), "r"(b1));
}

__device__ __forceinline__ uint32_t ldu(const float* p) {
  return __float_as_uint(*p);
}

__device__ __forceinline__ void cp16(void* smem_dst, const void* gmem_src) {
  uint32_t s = (uint32_t)__cvta_generic_to_shared(smem_dst);
  asm volatile("cp.async.cg.shared.global [%0], [%1], 16;\n"
               :: "r"(s), "l"(gmem_src));
}
}  // namespace

extern "C" __global__ void __launch_bounds__(NT, 1)
sdpa_kernel(const float* __restrict__ Q, const float* __restrict__ K,
            const float* __restrict__ V, float* __restrict__ out,
            float* __restrict__ attn)
{
  extern __shared__ char smem_raw[];
  Smem& sm = *reinterpret_cast<Smem*>(smem_raw);

  const int qt  = blockIdx.x;
  const int b   = blockIdx.y;
  const int tid = threadIdx.x;
  const int q0  = qt * TQ;

  const int wid  = tid >> 5;
  const int lane = tid & 31;
  const int wr   = wid >> 1;        // 0..3 (16-row band)
  const int wc   = wid & 1;         // 0..1
  const int gid  = lane >> 2;       // 0..7
  const int tig  = lane & 3;        // 0..3

  const float* Qb = Q + (size_t)b * kS * kD;
  const float* Kb = K + (size_t)b * kS * kD;
  const float* Vb = V + (size_t)b * kS * kD;
  float* outb  = out  + (size_t)b * kS * kD;
  float* attnb = attn + (size_t)b * kS * kS;

  const int ar0 = 16 * wr + gid;    // first mma row this thread owns

  // ---- prologue: issue cp.async for first K/V tile into buffer 0 ----
  const int ldr = tid >> 5, ldc = (tid & 31) * 4;   // 8 rows per pass of 256 thr
  {
    const float* Kg = Kb + (size_t)(qt * TK) * kD;
    const float* Vg = Vb + (size_t)(qt * TK) * kD;
#pragma unroll
    for (int it = 0; it < 8; ++it) {
      int r = ldr + it * 8;
      cp16(&sm.Ks[0][r][ldc], Kg + (size_t)r * kD + ldc);
      cp16(&sm.Vs[0][r][ldc], Vg + (size_t)r * kD + ldc);
    }
    asm volatile("cp.async.commit_group;\n");
  }

  // ---- Q fragments -> registers (tf32-rounded), once per block ----
  uint32_t qf[16][4];
  {
    const float* Qr0 = Qb + (size_t)(q0 + ar0) * kD;
    const float* Qr1 = Qr0 + 8 * kD;
#pragma unroll
    for (int s = 0; s < 16; ++s) {
      const int d = 8 * s + tig;
      qf[s][0] = f2tf32(Qr0[d]);
      qf[s][1] = f2tf32(Qr1[d]);
      qf[s][2] = f2tf32(Qr0[d + 4]);
      qf[s][3] = f2tf32(Qr1[d + 4]);
    }
  }
  if (tid < TQ) sm.Zs[tid] = (float)q0;   // masked ones from lower tiles

  float oacc[8][4];
#pragma unroll
  for (int j = 0; j < 8; ++j)
#pragma unroll
    for (int v = 0; v < 4; ++v) oacc[j][v] = 0.f;

  // ================= Phase 1: upper (incl diagonal) tiles =================
  int bs = 0;
  for (int kt = qt; kt < NKT; ++kt) {
    const int k0 = kt * TK;
    asm volatile("cp.async.wait_group 0;\n");
    __syncthreads();                       // tile bs ready; prev PV/Ps done

    // prefetch next tile into the other buffer (overlaps with compute below)
    if (kt + 1 < NKT) {
      const float* Kg = Kb + (size_t)(k0 + TK) * kD;
      const float* Vg = Vb + (size_t)(k0 + TK) * kD;
      float (*Kd)[DP] = sm.Ks[bs ^ 1];
      float (*Vd)[VP] = sm.Vs[bs ^ 1];
#pragma unroll
      for (int it = 0; it < 8; ++it) {
        int r = ldr + it * 8;
        cp16(&Kd[r][ldc], Kg + (size_t)r * kD + ldc);
        cp16(&Vd[r][ldc], Vg + (size_t)r * kD + ldc);
      }
      asm volatile("cp.async.commit_group;\n");
    }

    // ---- QK^T: warp tile rows 16*wr..+16, cols 32*wc..+32 ----
    float sacc[4][4];
#pragma unroll
    for (int j = 0; j < 4; ++j)
#pragma unroll
      for (int v = 0; v < 4; ++v) sacc[j][v] = 0.f;

    const float (*Kt)[DP] = sm.Ks[bs];
#pragma unroll
    for (int s = 0; s < 16; ++s) {
      const int d0 = 8 * s;
#pragma unroll
      for (int j = 0; j < 4; ++j) {
        const int c0 = 32 * wc + 8 * j + gid;
        uint32_t b0 = f2tf32(__uint_as_float(ldu(&Kt[c0][d0 + tig])));
        uint32_t b1 = f2tf32(__uint_as_float(ldu(&Kt[c0][d0 + tig + 4])));
        mma_tf32(sacc[j], qf[s][0], qf[s][1], qf[s][2], qf[s][3], b0, b1);
      }
    }

    // ---- mask + exp; direct attn store; Ps store; Z partial via shuffles ----
    const bool diag = (kt == qt);
    float rs0 = 0.f, rs1 = 0.f;
    const int r0 = ar0, r1 = ar0 + 8;
    float* arow0 = attnb + (size_t)(q0 + r0) * kS + k0;
    float* arow1 = attnb + (size_t)(q0 + r1) * kS + k0;
#pragma unroll
    for (int j = 0; j < 4; ++j) {
      const int c = 32 * wc + 8 * j + 2 * tig;
      float e00, e01, e10, e11;
      if (diag) {
        e00 = (c     > r0) ? __expf(sacc[j][0] * kScale) : 1.0f;
        e01 = (c + 1 > r0) ? __expf(sacc[j][1] * kScale) : 1.0f;
        e10 = (c     > r1) ? __expf(sacc[j][2] * kScale) : 1.0f;
        e11 = (c + 1 > r1) ? __expf(sacc[j][3] * kScale) : 1.0f;
      } else {
        e00 = __expf(sacc[j][0] * kScale);
        e01 = __expf(sacc[j][1] * kScale);
        e10 = __expf(sacc[j][2] * kScale);
        e11 = __expf(sacc[j][3] * kScale);
      }
      rs0 += e00 + e01;
      rs1 += e10 + e11;
      *reinterpret_cast<float2*>(arow0 + c) = make_float2(e00, e01);
      *reinterpret_cast<float2*>(arow1 + c) = make_float2(e10, e11);
      *reinterpret_cast<float2*>(&sm.Ps[r0][c]) =
          make_float2(__uint_as_float(f2tf32(e00)), __uint_as_float(f2tf32(e01)));
      *reinterpret_cast<float2*>(&sm.Ps[r1][c]) =
          make_float2(__uint_as_float(f2tf32(e10)), __uint_as_float(f2tf32(e11)));
    }
    // deterministic reduction over tig quad (fixed xor tree)
    rs0 += __shfl_xor_sync(0xffffffffu, rs0, 1, 4);
    rs0 += __shfl_xor_sync(0xffffffffu, rs0, 2, 4);
    rs1 += __shfl_xor_sync(0xffffffffu, rs1, 1, 4);
    rs1 += __shfl_xor_sync(0xffffffffu, rs1, 2, 4);
    if (tig == 0) { sm.Zp[wc][r0] = rs0; sm.Zp[wc][r1] = rs1; }
    __syncthreads();                       // Ps + Zp ready
    if (tid < TQ) sm.Zs[tid] += sm.Zp[0][tid] + sm.Zp[1][tid];

    // ---- PV: warp tile rows 16*wr..+16, out cols 64*wc..+64 ----
    const float (*Vt)[VP] = sm.Vs[bs];
#pragma unroll
    for (int kk = 0; kk < TK; kk += 8) {
      uint32_t a0 = ldu(&sm.Ps[r0][kk + tig]);
      uint32_t a1 = ldu(&sm.Ps[r1][kk + tig]);
      uint32_t a2 = ldu(&sm.Ps[r0][kk + tig + 4]);
      uint32_t a3 = ldu(&sm.Ps[r1][kk + tig + 4]);
#pragma unroll
      for (int j = 0; j < 8; ++j) {
        const int c0 = 64 * wc + 8 * j + gid;
        uint32_t b0 = f2tf32(__uint_as_float(ldu(&Vt[kk + tig][c0])));
        uint32_t b1 = f2tf32(__uint_as_float(ldu(&Vt[kk + tig + 4][c0])));
        mma_tf32(oacc[j], a0, a1, a2, a3, b0, b1);
      }
    }
    bs ^= 1;
  }

  // ================= Phase 2 =================
  __syncthreads();
  if (tid < TQ) sm.rZs[tid] = 1.0f / sm.Zs[tid];
  __syncthreads();

  // ---- lower tiles: V column sums (fp32) + attn = 1/Z fill ----
  const int vc    = tid & 127;
  const int vhalf = tid >> 7;
  float vpart = 0.f;
  const int tr = tid >> 4, tc = tid & 15;
  for (int kt = 0; kt < qt; ++kt) {
    const int k0 = kt * TK;
    __syncthreads();
    {
      const float4* Vg = reinterpret_cast<const float4*>(Vb + (size_t)k0 * kD);
#pragma unroll
      for (int it = 0; it < 8; ++it) {
        int idx = tid + it * NT;
        int r = idx >> 5, c4 = idx & 31;
        *reinterpret_cast<float4*>(&sm.Vs[0][r][c4 * 4]) = Vg[idx];
      }
    }
    __syncthreads();
#pragma unroll 8
    for (int r = 0; r < 32; ++r) vpart += sm.Vs[0][32 * vhalf + r][vc];
#pragma unroll
    for (int p = 0; p < 4; ++p) {
      const int r = tr + 16 * p;
      const float rz = sm.rZs[r];
      *reinterpret_cast<float4*>(&attnb[(size_t)(q0 + r) * kS + k0 + 4 * tc]) =
          make_float4(rz, rz, rz, rz);
    }
  }
  sm.Vps[vhalf][vc] = vpart;
  __syncthreads();
  if (tid < kD) sm.Vcsum[tid] = sm.Vps[0][tid] + sm.Vps[1][tid];
  __syncthreads();

  // ---- rescale upper tiles: attn *= 1/Z ----
  for (int kt = qt; kt < NKT; ++kt) {
    const int k0 = kt * TK;
#pragma unroll
    for (int p = 0; p < 4; ++p) {
      const int r = tr + 16 * p;
      const float rz = sm.rZs[r];
      float4* a = reinterpret_cast<float4*>(
          &attnb[(size_t)(q0 + r) * kS + k0 + 4 * tc]);
      float4 v = *a;
      v.x *= rz; v.y *= rz; v.z *= rz; v.w *= rz;
      *a = v;
    }
  }

  // ---- final output ----
  {
    const int r0 = ar0, r1 = ar0 + 8;
    const float rz0 = sm.rZs[r0], rz1 = sm.rZs[r1];
#pragma unroll
    for (int j = 0; j < 8; ++j) {
      const int c = 64 * wc + 8 * j + 2 * tig;
      const float vs0 = sm.Vcsum[c], vs1 = sm.Vcsum[c + 1];
      float2 o0 = make_float2(rz0 * (oacc[j][0] + vs0),
                              rz0 * (oacc[j][1] + vs1));
      float2 o1 = make_float2(rz1 * (oacc[j][2] + vs0),
                              rz1 * (oacc[j][3] + vs1));
      *reinterpret_cast<float2*>(&outb[(size_t)(q0 + r0) * kD + c]) = o0;
      *reinterpret_cast<float2*>(&outb[(size_t)(q0 + r1) * kD + c]) = o1;
    }
  }
}

extern "C" void kernel_launch(void* const* d_in, const int* in_sizes, int n_in,
                              void* d_out, int out_size) {
  (void)in_sizes; (void)n_in; (void)out_size;
  const float* Q = (const float*)d_in[0];
  const float* K = (const float*)d_in[1];
  const float* V = (const float*)d_in[2];
  float* out  = (float*)d_out;
  float* attn = out + (size_t)kB * kS * kD;

  cudaFuncSetAttribute(sdpa_kernel, cudaFuncAttributeMaxDynamicSharedMemorySize,
                       SMEM_BYTES);
  dim3 grid(NKT, kB);
  sdpa_kernel<<<grid, NT, SMEM_BYTES>>>(Q, K, V, out, attn);
}

// round 4
// speedup vs baseline: 3.0133x; 1.0965x over previous
#include <cuda_runtime.h>
#include <cstdint>
#include <cstddef>

namespace {
constexpr int kB = 16;
constexpr int kS = 2048;
constexpr int kD = 128;
constexpr int TQ = 64;
constexpr int TK = 64;
constexpr int NT = 512;            // 16 warps
constexpr int NKT = kS / TK;       // 32 k-tiles
constexpr int DP = kD + 4;         // K pitch 132
constexpr int VP = kD + 8;         // V pitch 136
constexpr int KP = TK + 4;         // P pitch 68
constexpr float kScale = 0.08838834764831845f;  // 1/sqrt(128)

struct Smem {
  float Ks[2][TK][DP];   // raw fp32 K tiles (double buffered)
  float Vs[2][TK][VP];   // raw fp32 V tiles (double buffered)
  float Ps[TQ][KP];      // tf32-rounded exp tile
  float Zs[TQ];
  float rZs[TQ];
  float Zp[4][TQ];       // per-warp-column Z partials
  float Vps[4][kD];
  float Vcsum[kD];
};
constexpr int SMEM_BYTES = (int)sizeof(Smem);

__device__ __forceinline__ uint32_t f2tf32(float f) {
  uint32_t u;
  asm("cvt.rna.tf32.f32 %0, %1;" : "=r"(u) : "f"(f));
  return u;
}

__device__ __forceinline__ void mma_tf32(float c[4], uint32_t a0, uint32_t a1,
                                         uint32_t a2, uint32_t a3,
                                         uint32_t b0, uint32_t b1) {
  asm volatile(
      "mma.sync.aligned.m16n8k8.row.col.f32.tf32.tf32.f32 "
      "{%0,%1,%2,%3}, {%4,%5,%6,%7}, {%8,%9}, {%0,%1,%2,%3};\n"
      : "+f"(c[0]), "+f"(c[1]), "+f"(c[2]), "+f"(c[3])
      : "r"(a0), "r"(a1), "r"(a2), "r"(a3), "r"(b0), "r"(b1));
}

__device__ __forceinline__ uint32_t ldu(const float* p) {
  return __float_as_uint(*p);
}

__device__ __forceinline__ void cp16(void* smem_dst, const void* gmem_src) {
  uint32_t s = (uint32_t)__cvta_generic_to_shared(smem_dst);
  asm volatile("cp.async.cg.shared.global [%0], [%1], 16;\n"
               :: "r"(s), "l"(gmem_src));
}
}  // namespace

extern "C" __global__ void __launch_bounds__(NT, 1)
sdpa_kernel(const float* __restrict__ Q, const float* __restrict__ K,
            const float* __restrict__ V, float* __restrict__ out,
            float* __restrict__ attn)
{
  extern __shared__ char smem_raw[];
  Smem& sm = *reinterpret_cast<Smem*>(smem_raw);

  const int qt  = blockIdx.x;
  const int b   = blockIdx.y;
  const int tid = threadIdx.x;
  const int q0  = qt * TQ;

  const int wid  = tid >> 5;        // 0..15
  const int lane = tid & 31;
  const int wr   = wid >> 2;        // 0..3  (16-row band)
  const int wc   = wid & 3;         // 0..3  (16-col QK band / 32-col PV band)
  const int gid  = lane >> 2;       // 0..7
  const int tig  = lane & 3;        // 0..3

  const float* Qb = Q + (size_t)b * kS * kD;
  const float* Kb = K + (size_t)b * kS * kD;
  const float* Vb = V + (size_t)b * kS * kD;
  float* outb  = out  + (size_t)b * kS * kD;
  float* attnb = attn + (size_t)b * kS * kS;

  const int ar0 = 16 * wr + gid;    // first mma row this thread owns
  const int r0 = ar0, r1 = ar0 + 8;

  // ---- prologue: cp.async first K/V tile into buffer 0 ----
  const int ldr = tid >> 5, ldc = (tid & 31) * 4;   // 16 rows per pass
  {
    const float* Kg = Kb + (size_t)(qt * TK) * kD;
    const float* Vg = Vb + (size_t)(qt * TK) * kD;
#pragma unroll
    for (int it = 0; it < 4; ++it) {
      int r = ldr + it * 16;
      cp16(&sm.Ks[0][r][ldc], Kg + (size_t)r * kD + ldc);
      cp16(&sm.Vs[0][r][ldc], Vg + (size_t)r * kD + ldc);
    }
    asm volatile("cp.async.commit_group;\n");
  }

  // ---- Q fragments -> registers (tf32), once per block (rows r0,r1) ----
  uint32_t qf[16][4];
  {
    const float* Qr0 = Qb + (size_t)(q0 + r0) * kD;
    const float* Qr1 = Qr0 + 8 * kD;
#pragma unroll
    for (int s = 0; s < 16; ++s) {
      const int d = 8 * s + tig;
      qf[s][0] = f2tf32(Qr0[d]);
      qf[s][1] = f2tf32(Qr1[d]);
      qf[s][2] = f2tf32(Qr0[d + 4]);
      qf[s][3] = f2tf32(Qr1[d + 4]);
    }
  }
  if (tid < TQ) sm.Zs[tid] = (float)q0;

  float oacc[4][4];
#pragma unroll
  for (int j = 0; j < 4; ++j)
#pragma unroll
    for (int v = 0; v < 4; ++v) oacc[j][v] = 0.f;

  // ================= Phase 1: upper (incl diagonal) tiles =================
  int bs = 0;
  for (int kt = qt; kt < NKT; ++kt) {
    const int k0 = kt * TK;
    asm volatile("cp.async.wait_group 0;\n");
    __syncthreads();

    // prefetch next tile
    if (kt + 1 < NKT) {
      const float* Kg = Kb + (size_t)(k0 + TK) * kD;
      const float* Vg = Vb + (size_t)(k0 + TK) * kD;
      float (*Kd)[DP] = sm.Ks[bs ^ 1];
      float (*Vd)[VP] = sm.Vs[bs ^ 1];
#pragma unroll
      for (int it = 0; it < 4; ++it) {
        int r = ldr + it * 16;
        cp16(&Kd[r][ldc], Kg + (size_t)r * kD + ldc);
        cp16(&Vd[r][ldc], Vg + (size_t)r * kD + ldc);
      }
      asm volatile("cp.async.commit_group;\n");
    }

    // ---- QK^T: warp tile rows 16*wr..+16, cols 16*wc..+16 ----
    float sacc[2][4];
#pragma unroll
    for (int j = 0; j < 2; ++j)
#pragma unroll
      for (int v = 0; v < 4; ++v) sacc[j][v] = 0.f;

    const float (*Kt)[DP] = sm.Ks[bs];
#pragma unroll
    for (int s = 0; s < 16; ++s) {
      const int d0 = 8 * s;
#pragma unroll
      for (int j = 0; j < 2; ++j) {
        const int c0 = 16 * wc + 8 * j + gid;
        uint32_t b0 = f2tf32(__uint_as_float(ldu(&Kt[c0][d0 + tig])));
        uint32_t b1 = f2tf32(__uint_as_float(ldu(&Kt[c0][d0 + tig + 4])));
        mma_tf32(sacc[j], qf[s][0], qf[s][1], qf[s][2], qf[s][3], b0, b1);
      }
    }

    // ---- mask + exp; direct attn store; Ps store; Z partials ----
    const bool diag = (kt == qt);
    float rs0 = 0.f, rs1 = 0.f;
    float* arow0 = attnb + (size_t)(q0 + r0) * kS + k0;
    float* arow1 = attnb + (size_t)(q0 + r1) * kS + k0;
#pragma unroll
    for (int j = 0; j < 2; ++j) {
      const int c = 16 * wc + 8 * j + 2 * tig;
      float e00, e01, e10, e11;
      if (diag) {
        e00 = (c     > r0) ? __expf(sacc[j][0] * kScale) : 1.0f;
        e01 = (c + 1 > r0) ? __expf(sacc[j][1] * kScale) : 1.0f;
        e10 = (c     > r1) ? __expf(sacc[j][2] * kScale) : 1.0f;
        e11 = (c + 1 > r1) ? __expf(sacc[j][3] * kScale) : 1.0f;
      } else {
        e00 = __expf(sacc[j][0] * kScale);
        e01 = __expf(sacc[j][1] * kScale);
        e10 = __expf(sacc[j][2] * kScale);
        e11 = __expf(sacc[j][3] * kScale);
      }
      rs0 += e00 + e01;
      rs1 += e10 + e11;
      *reinterpret_cast<float2*>(arow0 + c) = make_float2(e00, e01);
      *reinterpret_cast<float2*>(arow1 + c) = make_float2(e10, e11);
      *reinterpret_cast<float2*>(&sm.Ps[r0][c]) =
          make_float2(__uint_as_float(f2tf32(e00)), __uint_as_float(f2tf32(e01)));
      *reinterpret_cast<float2*>(&sm.Ps[r1][c]) =
          make_float2(__uint_as_float(f2tf32(e10)), __uint_as_float(f2tf32(e11)));
    }
    rs0 += __shfl_xor_sync(0xffffffffu, rs0, 1, 4);
    rs0 += __shfl_xor_sync(0xffffffffu, rs0, 2, 4);
    rs1 += __shfl_xor_sync(0xffffffffu, rs1, 1, 4);
    rs1 += __shfl_xor_sync(0xffffffffu, rs1, 2, 4);
    if (tig == 0) { sm.Zp[wc][r0] = rs0; sm.Zp[wc][r1] = rs1; }
    __syncthreads();
    if (tid < TQ)
      sm.Zs[tid] += (sm.Zp[0][tid] + sm.Zp[1][tid]) +
                    (sm.Zp[2][tid] + sm.Zp[3][tid]);

    // ---- PV: warp tile rows 16*wr..+16, out cols 32*wc..+32 ----
    const float (*Vt)[VP] = sm.Vs[bs];
#pragma unroll
    for (int kk = 0; kk < TK; kk += 8) {
      uint32_t a0 = ldu(&sm.Ps[r0][kk + tig]);
      uint32_t a1 = ldu(&sm.Ps[r1][kk + tig]);
      uint32_t a2 = ldu(&sm.Ps[r0][kk + tig + 4]);
      uint32_t a3 = ldu(&sm.Ps[r1][kk + tig + 4]);
#pragma unroll
      for (int j = 0; j < 4; ++j) {
        const int c0 = 32 * wc + 8 * j + gid;
        uint32_t b0 = f2tf32(__uint_as_float(ldu(&Vt[kk + tig][c0])));
        uint32_t b1 = f2tf32(__uint_as_float(ldu(&Vt[kk + tig + 4][c0])));
        mma_tf32(oacc[j], a0, a1, a2, a3, b0, b1);
      }
    }
    bs ^= 1;
  }

  // ================= Phase 2 =================
  __syncthreads();
  if (tid < TQ) sm.rZs[tid] = 1.0f / sm.Zs[tid];
  __syncthreads();

  // ---- lower tiles: V column sums + attn = 1/Z fill ----
  const int vc = tid & 127;
  const int vq = tid >> 7;           // 0..3, sums 16 rows each
  float vpart = 0.f;
  const int ftr = tid >> 4, ftc = tid & 15;   // fill: 32 row-slots x 16 col4
  for (int kt = 0; kt < qt; ++kt) {
    const int k0 = kt * TK;
    __syncthreads();
    {
      const float4* Vg = reinterpret_cast<const float4*>(Vb + (size_t)k0 * kD);
#pragma unroll
      for (int it = 0; it < 4; ++it) {
        int idx = tid + it * NT;
        int r = idx >> 5, c4 = idx & 31;
        *reinterpret_cast<float4*>(&sm.Vs[0][r][c4 * 4]) = Vg[idx];
      }
    }
    __syncthreads();
#pragma unroll 8
    for (int r = 0; r < 16; ++r) vpart += sm.Vs[0][16 * vq + r][vc];
#pragma unroll
    for (int p = 0; p < 2; ++p) {
      const int r = ftr + 32 * p;
      const float rz = sm.rZs[r];
      *reinterpret_cast<float4*>(&attnb[(size_t)(q0 + r) * kS + k0 + 4 * ftc]) =
          make_float4(rz, rz, rz, rz);
    }
  }
  sm.Vps[vq][vc] = vpart;
  __syncthreads();
  if (tid < kD)
    sm.Vcsum[tid] = (sm.Vps[0][tid] + sm.Vps[1][tid]) +
                    (sm.Vps[2][tid] + sm.Vps[3][tid]);
  __syncthreads();

  // ---- rescale upper tiles: attn *= 1/Z ----
  for (int kt = qt; kt < NKT; ++kt) {
    const int k0 = kt * TK;
#pragma unroll
    for (int p = 0; p < 2; ++p) {
      const int r = ftr + 32 * p;
      const float rz = sm.rZs[r];
      float4* a = reinterpret_cast<float4*>(
          &attnb[(size_t)(q0 + r) * kS + k0 + 4 * ftc]);
      float4 v = *a;
      v.x *= rz; v.y *= rz; v.z *= rz; v.w *= rz;
      *a = v;
    }
  }

  // ---- final output ----
  {
    const float rz0 = sm.rZs[r0], rz1 = sm.rZs[r1];
#pragma unroll
    for (int j = 0; j < 4; ++j) {
      const int c = 32 * wc + 8 * j + 2 * tig;
      const float vs0 = sm.Vcsum[c], vs1 = sm.Vcsum[c + 1];
      float2 o0 = make_float2(rz0 * (oacc[j][0] + vs0),
                              rz0 * (oacc[j][1] + vs1));
      float2 o1 = make_float2(rz1 * (oacc[j][2] + vs0),
                              rz1 * (oacc[j][3] + vs1));
      *reinterpret_cast<float2*>(&outb[(size_t)(q0 + r0) * kD + c]) = o0;
      *reinterpret_cast<float2*>(&outb[(size_t)(q0 + r1) * kD + c]) = o1;
    }
  }
}

extern "C" void kernel_launch(void* const* d_in, const int* in_sizes, int n_in,
                              void* d_out, int out_size) {
  (void)in_sizes; (void)n_in; (void)out_size;
  const float* Q = (const float*)d_in[0];
  const float* K = (const float*)d_in[1];
  const float* V = (const float*)d_in[2];
  float* out  = (float*)d_out;
  float* attn = out + (size_t)kB * kS * kD;

  cudaFuncSetAttribute(sdpa_kernel, cudaFuncAttributeMaxDynamicSharedMemorySize,
                       SMEM_BYTES);
  dim3 grid(NKT, kB);
  sdpa_kernel<<<grid, NT, SMEM_BYTES>>>(Q, K, V, out, attn);
}

// round 5
// speedup vs baseline: 3.0281x; 1.0049x over previous
#include <cuda_runtime.h>
#include <cstdint>
#include <cstddef>

namespace {
constexpr int kB = 16;
constexpr int kS = 2048;
constexpr int kD = 128;
constexpr int TQ = 64;
constexpr int TK = 64;
constexpr int NT = 512;            // 16 warps
constexpr int NKT = kS / TK;       // 32 k-tiles
constexpr int DP = kD + 4;         // K pitch 132
constexpr int VP = kD + 8;         // V pitch 136
constexpr int KP = TK + 4;         // P pitch 68
constexpr float kScale = 0.08838834764831845f;  // 1/sqrt(128)

struct Smem {
  float Ks[2][TK][DP];   // raw fp32 K tiles (double buffered)
  float Vs[2][TK][VP];   // raw fp32 V tiles (double buffered)
  float Ps[TQ][KP];      // tf32-rounded exp tile
  float Zs[TQ];
  float rZs[TQ];
  float Zp[4][TQ];       // per-warp-column Z partials
  float Vps[4][kD];
  float Vcsum[kD];
};
constexpr int SMEM_BYTES = (int)sizeof(Smem);

__device__ __forceinline__ uint32_t f2tf32(float f) {
  uint32_t u;
  asm("cvt.rna.tf32.f32 %0, %1;" : "=r"(u) : "f"(f));
  return u;
}

__device__ __forceinline__ void mma_tf32(float c[4], uint32_t a0, uint32_t a1,
                                         uint32_t a2, uint32_t a3,
                                         uint32_t b0, uint32_t b1) {
  asm volatile(
      "mma.sync.aligned.m16n8k8.row.col.f32.tf32.tf32.f32 "
      "{%0,%1,%2,%3}, {%4,%5,%6,%7}, {%8,%9}, {%0,%1,%2,%3};\n"
      : "+f"(c[0]), "+f"(c[1]), "+f"(c[2]), "+f"(c[3])
      : "r"(a0), "r"(a1), "r"(a2), "r"(a3), "r"(b0), "r"(b1));
}

__device__ __forceinline__ uint32_t ldu(const float* p) {
  return __float_as_uint(*p);
}

__device__ __forceinline__ void cp16(void* smem_dst, const void* gmem_src) {
  uint32_t s = (uint32_t)__cvta_generic_to_shared(smem_dst);
  asm volatile("cp.async.cg.shared.global [%0], [%1], 16;\n"
               :: "r"(s), "l"(gmem_src));
}
}  // namespace

extern "C" __global__ void __launch_bounds__(NT, 1)
sdpa_kernel(const float* __restrict__ Q, const float* __restrict__ K,
            const float* __restrict__ V, float* __restrict__ out,
            float* __restrict__ attn)
{
  extern __shared__ char smem_raw[];
  Smem& sm = *reinterpret_cast<Smem*>(smem_raw);

  const int qt  = blockIdx.x;
  const int b   = blockIdx.y;
  const int tid = threadIdx.x;
  const int q0  = qt * TQ;

  const int wid  = tid >> 5;        // 0..15
  const int lane = tid & 31;
  const int wr   = wid >> 2;        // 0..3  (16-row band)
  const int wc   = wid & 3;         // 0..3  (16-col QK band / 32-col PV band)
  const int gid  = lane >> 2;       // 0..7
  const int tig  = lane & 3;        // 0..3

  const float* Qb = Q + (size_t)b * kS * kD;
  const float* Kb = K + (size_t)b * kS * kD;
  const float* Vb = V + (size_t)b * kS * kD;
  float* outb  = out  + (size_t)b * kS * kD;
  float* attnb = attn + (size_t)b * kS * kS;

  const int ar0 = 16 * wr + gid;    // first mma row this thread owns
  const int r0 = ar0, r1 = ar0 + 8;

  // ---- prologue: cp.async first K/V tile into buffer 0 ----
  const int ldr = tid >> 5, ldc = (tid & 31) * 4;   // 16 rows per pass
  {
    const float* Kg = Kb + (size_t)(qt * TK) * kD;
    const float* Vg = Vb + (size_t)(qt * TK) * kD;
#pragma unroll
    for (int it = 0; it < 4; ++it) {
      int r = ldr + it * 16;
      cp16(&sm.Ks[0][r][ldc], Kg + (size_t)r * kD + ldc);
      cp16(&sm.Vs[0][r][ldc], Vg + (size_t)r * kD + ldc);
    }
    asm volatile("cp.async.commit_group;\n");
  }

  // ---- Q fragments -> registers (tf32), once per block (rows r0,r1) ----
  uint32_t qf[16][4];
  {
    const float* Qr0 = Qb + (size_t)(q0 + r0) * kD;
    const float* Qr1 = Qr0 + 8 * kD;
#pragma unroll
    for (int s = 0; s < 16; ++s) {
      const int d = 8 * s + tig;
      qf[s][0] = f2tf32(Qr0[d]);
      qf[s][1] = f2tf32(Qr1[d]);
      qf[s][2] = f2tf32(Qr0[d + 4]);
      qf[s][3] = f2tf32(Qr1[d + 4]);
    }
  }
  if (tid < TQ) sm.Zs[tid] = (float)q0;

  float oacc[4][4];
#pragma unroll
  for (int j = 0; j < 4; ++j)
#pragma unroll
    for (int v = 0; v < 4; ++v) oacc[j][v] = 0.f;

  // ================= Phase 1: upper (incl diagonal) tiles =================
  int bs = 0;
  for (int kt = qt; kt < NKT; ++kt) {
    const int k0 = kt * TK;
    asm volatile("cp.async.wait_group 0;\n");
    __syncthreads();

    // prefetch next tile
    if (kt + 1 < NKT) {
      const float* Kg = Kb + (size_t)(k0 + TK) * kD;
      const float* Vg = Vb + (size_t)(k0 + TK) * kD;
      float (*Kd)[DP] = sm.Ks[bs ^ 1];
      float (*Vd)[VP] = sm.Vs[bs ^ 1];
#pragma unroll
      for (int it = 0; it < 4; ++it) {
        int r = ldr + it * 16;
        cp16(&Kd[r][ldc], Kg + (size_t)r * kD + ldc);
        cp16(&Vd[r][ldc], Vg + (size_t)r * kD + ldc);
      }
      asm volatile("cp.async.commit_group;\n");
    }

    // ---- QK^T: warp tile rows 16*wr..+16, cols 16*wc..+16 ----
    float sacc[2][4];
#pragma unroll
    for (int j = 0; j < 2; ++j)
#pragma unroll
      for (int v = 0; v < 4; ++v) sacc[j][v] = 0.f;

    const float (*Kt)[DP] = sm.Ks[bs];
#pragma unroll
    for (int s = 0; s < 16; ++s) {
      const int d0 = 8 * s;
#pragma unroll
      for (int j = 0; j < 2; ++j) {
        const int c0 = 16 * wc + 8 * j + gid;
        uint32_t b0 = f2tf32(__uint_as_float(ldu(&Kt[c0][d0 + tig])));
        uint32_t b1 = f2tf32(__uint_as_float(ldu(&Kt[c0][d0 + tig + 4])));
        mma_tf32(sacc[j], qf[s][0], qf[s][1], qf[s][2], qf[s][3], b0, b1);
      }
    }

    // ---- mask + exp; direct attn store; Ps store; Z partials ----
    const bool diag = (kt == qt);
    float rs0 = 0.f, rs1 = 0.f;
    float* arow0 = attnb + (size_t)(q0 + r0) * kS + k0;
    float* arow1 = attnb + (size_t)(q0 + r1) * kS + k0;
#pragma unroll
    for (int j = 0; j < 2; ++j) {
      const int c = 16 * wc + 8 * j + 2 * tig;
      float e00, e01, e10, e11;
      if (diag) {
        e00 = (c     > r0) ? __expf(sacc[j][0] * kScale) : 1.0f;
        e01 = (c + 1 > r0) ? __expf(sacc[j][1] * kScale) : 1.0f;
        e10 = (c     > r1) ? __expf(sacc[j][2] * kScale) : 1.0f;
        e11 = (c + 1 > r1) ? __expf(sacc[j][3] * kScale) : 1.0f;
      } else {
        e00 = __expf(sacc[j][0] * kScale);
        e01 = __expf(sacc[j][1] * kScale);
        e10 = __expf(sacc[j][2] * kScale);
        e11 = __expf(sacc[j][3] * kScale);
      }
      rs0 += e00 + e01;
      rs1 += e10 + e11;
      *reinterpret_cast<float2*>(arow0 + c) = make_float2(e00, e01);
      *reinterpret_cast<float2*>(arow1 + c) = make_float2(e10, e11);
      *reinterpret_cast<float2*>(&sm.Ps[r0][c]) =
          make_float2(__uint_as_float(f2tf32(e00)), __uint_as_float(f2tf32(e01)));
      *reinterpret_cast<float2*>(&sm.Ps[r1][c]) =
          make_float2(__uint_as_float(f2tf32(e10)), __uint_as_float(f2tf32(e11)));
    }
    rs0 += __shfl_xor_sync(0xffffffffu, rs0, 1, 4);
    rs0 += __shfl_xor_sync(0xffffffffu, rs0, 2, 4);
    rs1 += __shfl_xor_sync(0xffffffffu, rs1, 1, 4);
    rs1 += __shfl_xor_sync(0xffffffffu, rs1, 2, 4);
    if (tig == 0) { sm.Zp[wc][r0] = rs0; sm.Zp[wc][r1] = rs1; }
    __syncthreads();
    if (tid < TQ)
      sm.Zs[tid] += (sm.Zp[0][tid] + sm.Zp[1][tid]) +
                    (sm.Zp[2][tid] + sm.Zp[3][tid]);

    // ---- PV: warp tile rows 16*wr..+16, out cols 32*wc..+32 ----
    const float (*Vt)[VP] = sm.Vs[bs];
#pragma unroll
    for (int kk = 0; kk < TK; kk += 8) {
      uint32_t a0 = ldu(&sm.Ps[r0][kk + tig]);
      uint32_t a1 = ldu(&sm.Ps[r1][kk + tig]);
      uint32_t a2 = ldu(&sm.Ps[r0][kk + tig + 4]);
      uint32_t a3 = ldu(&sm.Ps[r1][kk + tig + 4]);
#pragma unroll
      for (int j = 0; j < 4; ++j) {
        const int c0 = 32 * wc + 8 * j + gid;
        uint32_t b0 = f2tf32(__uint_as_float(ldu(&Vt[kk + tig][c0])));
        uint32_t b1 = f2tf32(__uint_as_float(ldu(&Vt[kk + tig + 4][c0])));
        mma_tf32(oacc[j], a0, a1, a2, a3, b0, b1);
      }
    }
    bs ^= 1;
  }

  // ================= Phase 2 =================
  __syncthreads();
  if (tid < TQ) sm.rZs[tid] = 1.0f / sm.Zs[tid];
  __syncthreads();

  // ---- lower tiles: V column sums + attn = 1/Z fill ----
  const int vc = tid & 127;
  const int vq = tid >> 7;           // 0..3, sums 16 rows each
  float vpart = 0.f;
  const int ftr = tid >> 4, ftc = tid & 15;   // fill: 32 row-slots x 16 col4
  for (int kt = 0; kt < qt; ++kt) {
    const int k0 = kt * TK;
    __syncthreads();
    {
      const float4* Vg = reinterpret_cast<const float4*>(Vb + (size_t)k0 * kD);
#pragma unroll
      for (int it = 0; it < 4; ++it) {
        int idx = tid + it * NT;
        int r = idx >> 5, c4 = idx & 31;
        *reinterpret_cast<float4*>(&sm.Vs[0][r][c4 * 4]) = Vg[idx];
      }
    }
    __syncthreads();
#pragma unroll 8
    for (int r = 0; r < 16; ++r) vpart += sm.Vs[0][16 * vq + r][vc];
#pragma unroll
    for (int p = 0; p < 2; ++p) {
      const int r = ftr + 32 * p;
      const float rz = sm.rZs[r];
      *reinterpret_cast<float4*>(&attnb[(size_t)(q0 + r) * kS + k0 + 4 * ftc]) =
          make_float4(rz, rz, rz, rz);
    }
  }
  sm.Vps[vq][vc] = vpart;
  __syncthreads();
  if (tid < kD)
    sm.Vcsum[tid] = (sm.Vps[0][tid] + sm.Vps[1][tid]) +
                    (sm.Vps[2][tid] + sm.Vps[3][tid]);
  __syncthreads();

  // ---- rescale upper tiles: attn *= 1/Z ----
  for (int kt = qt; kt < NKT; ++kt) {
    const int k0 = kt * TK;
#pragma unroll
    for (int p = 0; p < 2; ++p) {
      const int r = ftr + 32 * p;
      const float rz = sm.rZs[r];
      float4* a = reinterpret_cast<float4*>(
          &attnb[(size_t)(q0 + r) * kS + k0 + 4 * ftc]);
      float4 v = *a;
      v.x *= rz; v.y *= rz; v.z *= rz; v.w *= rz;
      *a = v;
    }
  }

  // ---- final output ----
  {
    const float rz0 = sm.rZs[r0], rz1 = sm.rZs[r1];
#pragma unroll
    for (int j = 0; j < 4; ++j) {
      const int c = 32 * wc + 8 * j + 2 * tig;
      const float vs0 = sm.Vcsum[c], vs1 = sm.Vcsum[c + 1];
      float2 o0 = make_float2(rz0 * (oacc[j][0] + vs0),
                              rz0 * (oacc[j][1] + vs1));
      float2 o1 = make_float2(rz1 * (oacc[j][2] + vs0),
                              rz1 * (oacc[j][3] + vs1));
      *reinterpret_cast<float2*>(&outb[(size_t)(q0 + r0) * kD + c]) = o0;
      *reinterpret_cast<float2*>(&outb[(size_t)(q0 + r1) * kD + c]) = o1;
    }
  }
}

extern "C" void kernel_launch(void* const* d_in, const int* in_sizes, int n_in,
                              void* d_out, int out_size) {
  (void)in_sizes; (void)n_in; (void)out_size;
  const float* Q = (const float*)d_in[0];
  const float* K = (const float*)d_in[1];
  const float* V = (const float*)d_in[2];
  float* out  = (float*)d_out;
  float* attn = out + (size_t)kB * kS * kD;

  cudaFuncSetAttribute(sdpa_kernel, cudaFuncAttributeMaxDynamicSharedMemorySize,
                       SMEM_BYTES);
  dim3 grid(NKT, kB);
  sdpa_kernel<<<grid, NT, SMEM_BYTES>>>(Q, K, V, out, attn);
}